// round 1
// baseline (speedup 1.0000x reference)
#include <cuda_runtime.h>
#include <cuda_bf16.h>

// Problem constants
#define BB   32
#define LL   512
#define DD   256
#define KKB  6
#define MTOK (BB * LL)   // 16384 tokens
#define HID  (4 * DD)    // 1024

// ---------------------------------------------------------------------------
// Scratch (static __device__ arrays: allocation-guard safe)
// ---------------------------------------------------------------------------
__device__ float g_emb[MTOK * DD];   // [L][B][D] layout (matches output layout)
__device__ float g_x  [MTOK * DD];   // [token][D], token = b*L + l
__device__ float g_h  [MTOK * HID];  // hidden activations
__device__ float g_x2 [MTOK * DD];
__device__ float g_x3 [MTOK * DD];
__device__ float g_msg[MTOK * DD];

// ---------------------------------------------------------------------------
// Embedding sum: emb[l,b,d] = elem + pe + aroma + charge(+6) + seg + react
// Writes both g_emb ([L][B][D]) and g_x ([token][D]).
// 4 tokens per 256-thread block, 64 threads x float4 per token.
// ---------------------------------------------------------------------------
__global__ __launch_bounds__(256) void embed_kernel(
    const int* __restrict__ element, const int* __restrict__ aroma,
    const int* __restrict__ charge,  const int* __restrict__ segment,
    const int* __restrict__ rmask,
    const float* __restrict__ elem_emb, const float* __restrict__ charge_emb,
    const float* __restrict__ aroma_emb, const float* __restrict__ react_emb,
    const float* __restrict__ seg_emb,   const float* __restrict__ pe)
{
    const int token = blockIdx.x * 4 + (threadIdx.x >> 6);
    const int c     = (threadIdx.x & 63) * 4;
    const int b     = token >> 9;      // / LL
    const int l     = token & (LL - 1);

    const int e  = __ldg(&element[token]);
    const int a  = __ldg(&aroma[token]);
    const int ch = __ldg(&charge[token]) + 6;
    const int s  = __ldg(&segment[token]);
    const int r  = __ldg(&rmask[token]);

    float4 v = *(const float4*)(elem_emb + e * DD + c);
    float4 t;
    t = *(const float4*)(pe + l * DD + c);          v.x += t.x; v.y += t.y; v.z += t.z; v.w += t.w;
    t = *(const float4*)(aroma_emb + a * DD + c);   v.x += t.x; v.y += t.y; v.z += t.z; v.w += t.w;
    t = *(const float4*)(charge_emb + ch * DD + c); v.x += t.x; v.y += t.y; v.z += t.z; v.w += t.w;
    t = *(const float4*)(seg_emb + s * DD + c);     v.x += t.x; v.y += t.y; v.z += t.z; v.w += t.w;
    t = *(const float4*)(react_emb + r * DD + c);   v.x += t.x; v.y += t.y; v.z += t.z; v.w += t.w;

    *(float4*)(g_emb + (l * BB + b) * DD + c) = v;
    *(float4*)(g_x   + token * DD + c)        = v;
}

// ---------------------------------------------------------------------------
// Register-blocked SGEMM:  C[M,N] = A[M,K] * W[N,K]^T + bias (+res) (ReLU opt.)
// BM=128, BK=16, TM=8; BN/TN templated (128/8 or 64/4). 256 threads.
// M, N, K all divisible by tile sizes -> no bounds checks.
// ---------------------------------------------------------------------------
template<int BN, int TN, bool RELU, bool RES>
__global__ __launch_bounds__(256) void sgemm_kernel(
    const float* __restrict__ A, const float* __restrict__ W,
    const float* __restrict__ bias, const float* __restrict__ res,
    float* __restrict__ C, int N, int K)
{
    constexpr int BM = 128, BK = 16, TM = 8;
    __shared__ float As[BK][BM + 4];   // +4 pad: kill 4-way store conflicts
    __shared__ float Bs[BK][BN + 4];

    const int tid = threadIdx.x;
    const int tm  = tid / (BN / TN);   // 0..15
    const int tn  = tid % (BN / TN);   // 0..15
    const int rowBase = blockIdx.y * BM;
    const int colBase = blockIdx.x * BN;

    float acc[TM][TN];
    #pragma unroll
    for (int i = 0; i < TM; i++)
        #pragma unroll
        for (int j = 0; j < TN; j++) acc[i][j] = 0.f;

    const float* Ab = A + (size_t)rowBase * K;
    const float* Wb = W + (size_t)colBase * K;

    for (int k0 = 0; k0 < K; k0 += BK) {
        // A tile: BM x BK = 512 float4 -> 2 per thread
        #pragma unroll
        for (int i = 0; i < (BM * BK / 4) / 256; i++) {
            int v  = tid + i * 256;
            int r  = v >> 2;            // BK/4 = 4 k-groups per row
            int kg = (v & 3) << 2;
            float4 x = *(const float4*)(Ab + (size_t)r * K + k0 + kg);
            As[kg + 0][r] = x.x; As[kg + 1][r] = x.y;
            As[kg + 2][r] = x.z; As[kg + 3][r] = x.w;
        }
        // W tile: BN x BK
        #pragma unroll
        for (int i = 0; i < (BN * BK / 4) / 256; i++) {
            int v  = tid + i * 256;
            int r  = v >> 2;
            int kg = (v & 3) << 2;
            float4 x = *(const float4*)(Wb + (size_t)r * K + k0 + kg);
            Bs[kg + 0][r] = x.x; Bs[kg + 1][r] = x.y;
            Bs[kg + 2][r] = x.z; Bs[kg + 3][r] = x.w;
        }
        __syncthreads();

        #pragma unroll
        for (int k = 0; k < BK; k++) {
            float a[TM], bv[TN];
            #pragma unroll
            for (int i = 0; i < TM; i++) a[i] = As[k][tm * TM + i];
            #pragma unroll
            for (int j = 0; j < TN; j++) bv[j] = Bs[k][tn * TN + j];
            #pragma unroll
            for (int i = 0; i < TM; i++)
                #pragma unroll
                for (int j = 0; j < TN; j++)
                    acc[i][j] = fmaf(a[i], bv[j], acc[i][j]);
        }
        __syncthreads();
    }

    // Epilogue: bias (+residual) (+relu), float4 stores
    #pragma unroll
    for (int i = 0; i < TM; i++) {
        const int row = rowBase + tm * TM + i;
        #pragma unroll
        for (int j0 = 0; j0 < TN; j0 += 4) {
            const int col = colBase + tn * TN + j0;
            float4 v;
            v.x = acc[i][j0 + 0] + __ldg(&bias[col + 0]);
            v.y = acc[i][j0 + 1] + __ldg(&bias[col + 1]);
            v.z = acc[i][j0 + 2] + __ldg(&bias[col + 2]);
            v.w = acc[i][j0 + 3] + __ldg(&bias[col + 3]);
            if (RES) {
                float4 rr = *(const float4*)(res + (size_t)row * N + col);
                v.x += rr.x; v.y += rr.y; v.z += rr.z; v.w += rr.w;
            }
            if (RELU) {
                v.x = fmaxf(v.x, 0.f); v.y = fmaxf(v.y, 0.f);
                v.z = fmaxf(v.z, 0.f); v.w = fmaxf(v.w, 0.f);
            }
            *(float4*)(C + (size_t)row * N + col) = v;
        }
    }
}

// ---------------------------------------------------------------------------
// Bond aggregation + output:
// out[l,b,d] = emb[l,b,d] + sum_{k<6, bond!=l} msg[b, bond[b,l,k], d]
// ---------------------------------------------------------------------------
__global__ __launch_bounds__(256) void agg_kernel(
    const int* __restrict__ bond, float* __restrict__ out)
{
    const int token = blockIdx.x * 4 + (threadIdx.x >> 6);
    const int c     = (threadIdx.x & 63) * 4;
    const int b     = token >> 9;
    const int l     = token & (LL - 1);

    float4 acc = *(const float4*)(g_emb + (l * BB + b) * DD + c);
    const int* bd = bond + token * KKB;
    #pragma unroll
    for (int k = 0; k < KKB; k++) {
        const int j = __ldg(&bd[k]);
        if (j != l) {
            float4 m = *(const float4*)(g_msg + ((size_t)b * LL + j) * DD + c);
            acc.x += m.x; acc.y += m.y; acc.z += m.z; acc.w += m.w;
        }
    }
    *(float4*)(out + (l * BB + b) * DD + c) = acc;
}

// ---------------------------------------------------------------------------
// Launch (graph-capturable: kernel launches on default stream only)
// ---------------------------------------------------------------------------
extern "C" void kernel_launch(void* const* d_in, const int* in_sizes, int n_in,
                              void* d_out, int out_size)
{
    const int*   element    = (const int*)  d_in[0];
    const int*   bond       = (const int*)  d_in[1];
    const int*   aroma      = (const int*)  d_in[2];
    const int*   charge     = (const int*)  d_in[3];
    const int*   segment    = (const int*)  d_in[4];
    const int*   rmask      = (const int*)  d_in[5];
    const float* elem_emb   = (const float*)d_in[6];
    const float* charge_emb = (const float*)d_in[7];
    const float* aroma_emb  = (const float*)d_in[8];
    const float* react_emb  = (const float*)d_in[9];
    const float* seg_emb    = (const float*)d_in[10];
    const float* pe         = (const float*)d_in[11];
    const float* w1 = (const float*)d_in[12];
    const float* b1 = (const float*)d_in[13];
    const float* w2 = (const float*)d_in[14];
    const float* b2 = (const float*)d_in[15];
    const float* w3 = (const float*)d_in[16];
    const float* b3 = (const float*)d_in[17];
    const float* w4 = (const float*)d_in[18];
    const float* b4 = (const float*)d_in[19];
    const float* w5 = (const float*)d_in[20];
    const float* b5 = (const float*)d_in[21];

    float *x, *h, *x2, *x3, *msg;
    cudaGetSymbolAddress((void**)&x,   g_x);
    cudaGetSymbolAddress((void**)&h,   g_h);
    cudaGetSymbolAddress((void**)&x2,  g_x2);
    cudaGetSymbolAddress((void**)&x3,  g_x3);
    cudaGetSymbolAddress((void**)&msg, g_msg);

    // 1) embedding sum
    embed_kernel<<<MTOK / 4, 256>>>(element, aroma, charge, segment, rmask,
                                    elem_emb, charge_emb, aroma_emb,
                                    react_emb, seg_emb, pe);

    // 2) MLP block 1: h = relu(x @ w1^T + b1); x2 = x + h @ w2^T + b2
    sgemm_kernel<128, 8, true,  false><<<dim3(HID / 128, MTOK / 128), 256>>>(
        x, w1, b1, nullptr, h, HID, DD);
    sgemm_kernel<64,  4, false, true ><<<dim3(DD / 64,   MTOK / 128), 256>>>(
        h, w2, b2, x, x2, DD, HID);

    // 3) MLP block 2: h = relu(x2 @ w3^T + b3); x3 = x2 + h @ w4^T + b4
    sgemm_kernel<128, 8, true,  false><<<dim3(HID / 128, MTOK / 128), 256>>>(
        x2, w3, b3, nullptr, h, HID, DD);
    sgemm_kernel<64,  4, false, true ><<<dim3(DD / 64,   MTOK / 128), 256>>>(
        h, w4, b4, x2, x3, DD, HID);

    // 4) msg = x3 @ w5^T + b5
    sgemm_kernel<64,  4, false, false><<<dim3(DD / 64,   MTOK / 128), 256>>>(
        x3, w5, b5, nullptr, msg, DD, DD);

    // 5) out = emb + masked bond aggregation of msg
    agg_kernel<<<MTOK / 4, 256>>>(bond, (float*)d_out);
}

// round 4
// speedup vs baseline: 3.3445x; 3.3445x over previous
#include <cuda_runtime.h>
#include <cuda_bf16.h>
#include <cstdint>

// Problem constants
#define BB   32
#define LL   512
#define DD   256
#define KKB  6
#define MTOK (BB * LL)   // 16384 tokens
#define HID  (4 * DD)    // 1024

// ---------------------------------------------------------------------------
// Scratch (static __device__ arrays: allocation-guard safe)
// ---------------------------------------------------------------------------
__device__ float g_emb[MTOK * DD];   // [L][B][D] layout (matches output layout)
__device__ float g_x  [MTOK * DD];   // [token][D], token = b*L + l
__device__ float g_h  [MTOK * HID];  // hidden activations
__device__ float g_x2 [MTOK * DD];
__device__ float g_x3 [MTOK * DD];
__device__ float g_msg[MTOK * DD];

// ---------------------------------------------------------------------------
// PTX helpers (sm_80-compatible only: cp.async, ldmatrix, mma.sync)
// ---------------------------------------------------------------------------
__device__ __forceinline__ uint32_t smem_u32(const void* p) {
    uint32_t a;
    asm("{ .reg .u64 t; cvta.to.shared.u64 t, %1; cvt.u32.u64 %0, t; }"
        : "=r"(a) : "l"(p));
    return a;
}

__device__ __forceinline__ void cpasync16(uint32_t s, const void* g) {
    asm volatile("cp.async.cg.shared.global [%0], [%1], 16;" :: "r"(s), "l"(g));
}
#define CP_COMMIT() asm volatile("cp.async.commit_group;" ::: "memory")
template<int N> __device__ __forceinline__ void cpwait() {
    asm volatile("cp.async.wait_group %0;" :: "n"(N) : "memory");
}

__device__ __forceinline__ void ldsm4(uint32_t* r, uint32_t addr) {
    asm volatile("ldmatrix.sync.aligned.m8n8.x4.shared.b16 {%0,%1,%2,%3}, [%4];"
        : "=r"(r[0]), "=r"(r[1]), "=r"(r[2]), "=r"(r[3]) : "r"(addr));
}

__device__ __forceinline__ void cvt_tf32(uint32_t& x) {
    asm("cvt.rna.tf32.f32 %0, %0;" : "+r"(x));
}

__device__ __forceinline__ void mma_tf32(float* d, const uint32_t* a, const uint32_t* b) {
    asm volatile(
        "mma.sync.aligned.m16n8k8.row.col.f32.tf32.tf32.f32 "
        "{%0,%1,%2,%3}, {%4,%5,%6,%7}, {%8,%9}, {%0,%1,%2,%3};"
        : "+f"(d[0]), "+f"(d[1]), "+f"(d[2]), "+f"(d[3])
        : "r"(a[0]), "r"(a[1]), "r"(a[2]), "r"(a[3]), "r"(b[0]), "r"(b[1]));
}

// ---------------------------------------------------------------------------
// Embedding sum kernel (unchanged; exact fp32)
// ---------------------------------------------------------------------------
__global__ __launch_bounds__(256) void embed_kernel(
    const int* __restrict__ element, const int* __restrict__ aroma,
    const int* __restrict__ charge,  const int* __restrict__ segment,
    const int* __restrict__ rmask,
    const float* __restrict__ elem_emb, const float* __restrict__ charge_emb,
    const float* __restrict__ aroma_emb, const float* __restrict__ react_emb,
    const float* __restrict__ seg_emb,   const float* __restrict__ pe)
{
    const int token = blockIdx.x * 4 + (threadIdx.x >> 6);
    const int c     = (threadIdx.x & 63) * 4;
    const int b     = token >> 9;
    const int l     = token & (LL - 1);

    const int e  = __ldg(&element[token]);
    const int a  = __ldg(&aroma[token]);
    const int ch = __ldg(&charge[token]) + 6;
    const int s  = __ldg(&segment[token]);
    const int r  = __ldg(&rmask[token]);

    float4 v = *(const float4*)(elem_emb + e * DD + c);
    float4 t;
    t = *(const float4*)(pe + l * DD + c);          v.x += t.x; v.y += t.y; v.z += t.z; v.w += t.w;
    t = *(const float4*)(aroma_emb + a * DD + c);   v.x += t.x; v.y += t.y; v.z += t.z; v.w += t.w;
    t = *(const float4*)(charge_emb + ch * DD + c); v.x += t.x; v.y += t.y; v.z += t.z; v.w += t.w;
    t = *(const float4*)(seg_emb + s * DD + c);     v.x += t.x; v.y += t.y; v.z += t.z; v.w += t.w;
    t = *(const float4*)(react_emb + r * DD + c);   v.x += t.x; v.y += t.y; v.z += t.z; v.w += t.w;

    *(float4*)(g_emb + (l * BB + b) * DD + c) = v;
    *(float4*)(g_x   + token * DD + c)        = v;
}

// ---------------------------------------------------------------------------
// TF32 tensor-core GEMM via mma.sync (sm_80 path; works on plain sm_100):
//   C[M,N] = A[M,K] @ W[N,K]^T + bias (+res) (+relu)
// BM=128, BN=128, BK=16, 4-stage cp.async pipeline, 256 threads (8 warps),
// warp tile 64x32 via m16n8k8 tf32 mma. Smem rows are 64B (16 floats) with a
// 16B-chunk xor swizzle: phys_chunk = c ^ ((row>>1)&3) -> ldmatrix conflict-free.
// ---------------------------------------------------------------------------
#define BM     128
#define BN     128
#define BK     16
#define STAGES 4
#define STG_SZ 16384            // (BM + BN) * BK * 4 bytes
#define SMEM_SZ (STAGES * STG_SZ)   // 65536

template<bool RELU, bool RES>
__global__ __launch_bounds__(256, 2) void tgemm_kernel(
    const float* __restrict__ A, const float* __restrict__ W,
    const float* __restrict__ bias, const float* __restrict__ res,
    float* __restrict__ C, int N, int K)
{
    extern __shared__ char smem[];
    const uint32_t sbase = smem_u32(smem);
    const int tid = threadIdx.x;
    const int wid = tid >> 5;
    const int lid = tid & 31;
    const int wm  = wid & 1;        // warp row: 2 x 64
    const int wn  = wid >> 1;       // warp col: 4 x 32

    const int rowBase = blockIdx.y * BM;
    const int colBase = blockIdx.x * BN;

    const int NC = K / BK;

    // ---- stage loader: A tile 128x16 f32 (8KB) + B tile 128x16 f32 (8KB) ----
    auto load_stage = [&](int c) {
        const int k0 = c * BK;
        const uint32_t sA = sbase + (c % STAGES) * STG_SZ;
        const uint32_t sB = sA + 8192;
        const float* Ag = A + (size_t)rowBase * K + k0;
        const float* Wg = W + (size_t)colBase * K + k0;
        #pragma unroll
        for (int p = 0; p < 2; p++) {              // 512 chunks / 256 thr
            int v = tid + p * 256;
            int r = v >> 2, ck = v & 3;
            cpasync16(sA + r * 64 + ((ck ^ ((r >> 1) & 3)) * 16),
                      Ag + (size_t)r * K + ck * 4);
        }
        #pragma unroll
        for (int p = 0; p < 2; p++) {
            int v = tid + p * 256;
            int r = v >> 2, ck = v & 3;
            cpasync16(sB + r * 64 + ((ck ^ ((r >> 1) & 3)) * 16),
                      Wg + (size_t)r * K + ck * 4);
        }
        CP_COMMIT();
    };

    float acc[4][4][4];
    #pragma unroll
    for (int mi = 0; mi < 4; mi++)
        #pragma unroll
        for (int ni = 0; ni < 4; ni++)
            #pragma unroll
            for (int j = 0; j < 4; j++) acc[mi][ni][j] = 0.f;

    // per-thread ldmatrix address components
    const int t   = lid & 7;
    const int sel = lid >> 3;
    // A: matrix sel: bit0 -> +8 rows, bit1 -> +1 k-chunk
    int aRow[4], aXor[4];
    #pragma unroll
    for (int mi = 0; mi < 4; mi++) {
        int r = wm * 64 + mi * 16 + (sel & 1) * 8 + t;
        aRow[mi] = r * 64;
        aXor[mi] = (r >> 1) & 3;
    }
    const int aCk = sel >> 1;
    // B: matrix sel: bit0 -> +1 k-chunk, bit1 -> +8 n-rows
    int bRow[2], bXor[2];
    #pragma unroll
    for (int np = 0; np < 2; np++) {
        int r = wn * 32 + np * 16 + (sel >> 1) * 8 + t;
        bRow[np] = r * 64;
        bXor[np] = (r >> 1) & 3;
    }
    const int bCk = sel & 1;

    // ---- pipeline prologue ----
    #pragma unroll
    for (int s = 0; s < STAGES - 1; s++) load_stage(s);

    for (int c = 0; c < NC; c++) {
        cpwait<STAGES - 2>();
        __syncthreads();
        if (c + STAGES - 1 < NC) load_stage(c + STAGES - 1);
        else CP_COMMIT();   // keep group count consistent

        const uint32_t sA = sbase + (c % STAGES) * STG_SZ;
        const uint32_t sB = sA + 8192;

        #pragma unroll
        for (int ks = 0; ks < 2; ks++) {
            uint32_t af[4][4], bf[2][4];
            #pragma unroll
            for (int mi = 0; mi < 4; mi++) {
                int ck = ks * 2 + aCk;
                ldsm4(af[mi], sA + aRow[mi] + ((ck ^ aXor[mi]) * 16));
            }
            #pragma unroll
            for (int np = 0; np < 2; np++) {
                int ck = ks * 2 + bCk;
                ldsm4(bf[np], sB + bRow[np] + ((ck ^ bXor[np]) * 16));
            }
            #pragma unroll
            for (int mi = 0; mi < 4; mi++)
                #pragma unroll
                for (int j = 0; j < 4; j++) cvt_tf32(af[mi][j]);
            #pragma unroll
            for (int np = 0; np < 2; np++)
                #pragma unroll
                for (int j = 0; j < 4; j++) cvt_tf32(bf[np][j]);

            #pragma unroll
            for (int mi = 0; mi < 4; mi++)
                #pragma unroll
                for (int ni = 0; ni < 4; ni++)
                    mma_tf32(acc[mi][ni], af[mi], &bf[ni >> 1][(ni & 1) * 2]);
        }
    }

    // ---- epilogue: bias (+res) (+relu), float2 stores ----
    const int g  = lid >> 2;
    const int tg = lid & 3;
    #pragma unroll
    for (int mi = 0; mi < 4; mi++) {
        const int row0 = rowBase + wm * 64 + mi * 16 + g;
        const int row1 = row0 + 8;
        #pragma unroll
        for (int ni = 0; ni < 4; ni++) {
            const int col = colBase + wn * 32 + ni * 8 + tg * 2;
            float bx = __ldg(&bias[col]), by = __ldg(&bias[col + 1]);
            float2 v0 = make_float2(acc[mi][ni][0] + bx, acc[mi][ni][1] + by);
            float2 v1 = make_float2(acc[mi][ni][2] + bx, acc[mi][ni][3] + by);
            if (RES) {
                float2 r0 = *(const float2*)(res + (size_t)row0 * N + col);
                float2 r1 = *(const float2*)(res + (size_t)row1 * N + col);
                v0.x += r0.x; v0.y += r0.y; v1.x += r1.x; v1.y += r1.y;
            }
            if (RELU) {
                v0.x = fmaxf(v0.x, 0.f); v0.y = fmaxf(v0.y, 0.f);
                v1.x = fmaxf(v1.x, 0.f); v1.y = fmaxf(v1.y, 0.f);
            }
            *(float2*)(C + (size_t)row0 * N + col) = v0;
            *(float2*)(C + (size_t)row1 * N + col) = v1;
        }
    }
}

// ---------------------------------------------------------------------------
// Bond aggregation + output (unchanged)
// ---------------------------------------------------------------------------
__global__ __launch_bounds__(256) void agg_kernel(
    const int* __restrict__ bond, float* __restrict__ out)
{
    const int token = blockIdx.x * 4 + (threadIdx.x >> 6);
    const int c     = (threadIdx.x & 63) * 4;
    const int b     = token >> 9;
    const int l     = token & (LL - 1);

    float4 acc = *(const float4*)(g_emb + (l * BB + b) * DD + c);
    const int* bd = bond + token * KKB;
    #pragma unroll
    for (int k = 0; k < KKB; k++) {
        const int j = __ldg(&bd[k]);
        if (j != l) {
            float4 m = *(const float4*)(g_msg + ((size_t)b * LL + j) * DD + c);
            acc.x += m.x; acc.y += m.y; acc.z += m.z; acc.w += m.w;
        }
    }
    *(float4*)(out + (l * BB + b) * DD + c) = acc;
}

// ---------------------------------------------------------------------------
// Launch (graph-capturable)
// ---------------------------------------------------------------------------
extern "C" void kernel_launch(void* const* d_in, const int* in_sizes, int n_in,
                              void* d_out, int out_size)
{
    const int*   element    = (const int*)  d_in[0];
    const int*   bond       = (const int*)  d_in[1];
    const int*   aroma      = (const int*)  d_in[2];
    const int*   charge     = (const int*)  d_in[3];
    const int*   segment    = (const int*)  d_in[4];
    const int*   rmask      = (const int*)  d_in[5];
    const float* elem_emb   = (const float*)d_in[6];
    const float* charge_emb = (const float*)d_in[7];
    const float* aroma_emb  = (const float*)d_in[8];
    const float* react_emb  = (const float*)d_in[9];
    const float* seg_emb    = (const float*)d_in[10];
    const float* pe         = (const float*)d_in[11];
    const float* w1 = (const float*)d_in[12];
    const float* b1 = (const float*)d_in[13];
    const float* w2 = (const float*)d_in[14];
    const float* b2 = (const float*)d_in[15];
    const float* w3 = (const float*)d_in[16];
    const float* b3 = (const float*)d_in[17];
    const float* w4 = (const float*)d_in[18];
    const float* b4 = (const float*)d_in[19];
    const float* w5 = (const float*)d_in[20];
    const float* b5 = (const float*)d_in[21];

    float *x, *h, *x2, *x3, *msg;
    cudaGetSymbolAddress((void**)&x,   g_x);
    cudaGetSymbolAddress((void**)&h,   g_h);
    cudaGetSymbolAddress((void**)&x2,  g_x2);
    cudaGetSymbolAddress((void**)&x3,  g_x3);
    cudaGetSymbolAddress((void**)&msg, g_msg);

    cudaFuncSetAttribute(tgemm_kernel<true,  false>,
                         cudaFuncAttributeMaxDynamicSharedMemorySize, SMEM_SZ);
    cudaFuncSetAttribute(tgemm_kernel<false, true >,
                         cudaFuncAttributeMaxDynamicSharedMemorySize, SMEM_SZ);
    cudaFuncSetAttribute(tgemm_kernel<false, false>,
                         cudaFuncAttributeMaxDynamicSharedMemorySize, SMEM_SZ);

    // 1) embedding sum
    embed_kernel<<<MTOK / 4, 256>>>(element, aroma, charge, segment, rmask,
                                    elem_emb, charge_emb, aroma_emb,
                                    react_emb, seg_emb, pe);

    // 2) MLP block 1: h = relu(x @ w1^T + b1); x2 = x + h @ w2^T + b2
    tgemm_kernel<true,  false><<<dim3(HID / BN, MTOK / BM), 256, SMEM_SZ>>>(
        x, w1, b1, nullptr, h, HID, DD);
    tgemm_kernel<false, true ><<<dim3(DD / BN,  MTOK / BM), 256, SMEM_SZ>>>(
        h, w2, b2, x, x2, DD, HID);

    // 3) MLP block 2
    tgemm_kernel<true,  false><<<dim3(HID / BN, MTOK / BM), 256, SMEM_SZ>>>(
        x2, w3, b3, nullptr, h, HID, DD);
    tgemm_kernel<false, true ><<<dim3(DD / BN,  MTOK / BM), 256, SMEM_SZ>>>(
        h, w4, b4, x2, x3, DD, HID);

    // 4) msg = x3 @ w5^T + b5
    tgemm_kernel<false, false><<<dim3(DD / BN,  MTOK / BM), 256, SMEM_SZ>>>(
        x3, w5, b5, nullptr, msg, DD, DD);

    // 5) out = emb + masked bond aggregation
    agg_kernel<<<MTOK / 4, 256>>>(bond, (float*)d_out);
}

// round 7
// speedup vs baseline: 3.5767x; 1.0694x over previous
#include <cuda_runtime.h>
#include <cuda_bf16.h>
#include <cstdint>

// Problem constants
#define BB   32
#define LL   512
#define DD   256
#define KKB  6
#define MTOK (BB * LL)   // 16384 tokens
#define HID  (4 * DD)    // 1024

// ---------------------------------------------------------------------------
// Scratch (static __device__ arrays: allocation-guard safe)
// ---------------------------------------------------------------------------
__device__ float g_emb[MTOK * DD];   // [L][B][D] layout (exact fp32)
__device__ float g_x  [MTOK * DD];   // [token][D], tf32-rounded
__device__ float g_h  [MTOK * HID];  // hidden activations (tf32-rounded)
__device__ float g_x2 [MTOK * DD];   // tf32-rounded
__device__ float g_x3 [MTOK * DD];   // tf32-rounded
__device__ float g_msg[MTOK * DD];   // exact fp32
// pre-rounded weights, concatenated: w1 | w2 | w3 | w4 | w5
#define WOFF_W1 0
#define WOFF_W2 262144
#define WOFF_W3 524288
#define WOFF_W4 786432
#define WOFF_W5 1048576
#define WTOTAL  1114112
__device__ float g_wr[WTOTAL];

// ---------------------------------------------------------------------------
// PTX helpers (sm_80-compatible only: cp.async, ldmatrix, mma.sync)
// ---------------------------------------------------------------------------
__device__ __forceinline__ uint32_t smem_u32(const void* p) {
    uint32_t a;
    asm("{ .reg .u64 t; cvta.to.shared.u64 t, %1; cvt.u32.u64 %0, t; }"
        : "=r"(a) : "l"(p));
    return a;
}

__device__ __forceinline__ void cpasync16(uint32_t s, const void* g) {
    asm volatile("cp.async.cg.shared.global [%0], [%1], 16;" :: "r"(s), "l"(g));
}
#define CP_COMMIT() asm volatile("cp.async.commit_group;" ::: "memory")
template<int N> __device__ __forceinline__ void cpwait() {
    asm volatile("cp.async.wait_group %0;" :: "n"(N) : "memory");
}

__device__ __forceinline__ void ldsm4(uint32_t* r, uint32_t addr) {
    asm volatile("ldmatrix.sync.aligned.m8n8.x4.shared.b16 {%0,%1,%2,%3}, [%4];"
        : "=r"(r[0]), "=r"(r[1]), "=r"(r[2]), "=r"(r[3]) : "r"(addr));
}

__device__ __forceinline__ float tf32r(float x) {
    uint32_t u = __float_as_uint(x);
    asm("cvt.rna.tf32.f32 %0, %0;" : "+r"(u));
    return __uint_as_float(u);
}

__device__ __forceinline__ void mma_tf32(float* d, const uint32_t* a, const uint32_t* b) {
    asm volatile(
        "mma.sync.aligned.m16n8k8.row.col.f32.tf32.tf32.f32 "
        "{%0,%1,%2,%3}, {%4,%5,%6,%7}, {%8,%9}, {%0,%1,%2,%3};"
        : "+f"(d[0]), "+f"(d[1]), "+f"(d[2]), "+f"(d[3])
        : "r"(a[0]), "r"(a[1]), "r"(a[2]), "r"(a[3]), "r"(b[0]), "r"(b[1]));
}

// ---------------------------------------------------------------------------
// Weight pre-rounding: round all 5 weight matrices to tf32 once.
// ---------------------------------------------------------------------------
__global__ __launch_bounds__(256) void round_w_kernel(
    const float* __restrict__ w1, const float* __restrict__ w2,
    const float* __restrict__ w3, const float* __restrict__ w4,
    const float* __restrict__ w5)
{
    const int i = blockIdx.x * 256 + threadIdx.x;      // float4 index
    const size_t idx = (size_t)i * 4;
    if (idx >= WTOTAL) return;
    const float* s; size_t base;
    if      (idx < WOFF_W2) { s = w1; base = WOFF_W1; }
    else if (idx < WOFF_W3) { s = w2; base = WOFF_W2; }
    else if (idx < WOFF_W4) { s = w3; base = WOFF_W3; }
    else if (idx < WOFF_W5) { s = w4; base = WOFF_W4; }
    else                    { s = w5; base = WOFF_W5; }
    float4 v = *(const float4*)(s + (idx - base));
    v.x = tf32r(v.x); v.y = tf32r(v.y); v.z = tf32r(v.z); v.w = tf32r(v.w);
    *(float4*)(g_wr + idx) = v;
}

// ---------------------------------------------------------------------------
// Embedding sum: g_emb exact; g_x tf32-rounded (GEMM input)
// ---------------------------------------------------------------------------
__global__ __launch_bounds__(256) void embed_kernel(
    const int* __restrict__ element, const int* __restrict__ aroma,
    const int* __restrict__ charge,  const int* __restrict__ segment,
    const int* __restrict__ rmask,
    const float* __restrict__ elem_emb, const float* __restrict__ charge_emb,
    const float* __restrict__ aroma_emb, const float* __restrict__ react_emb,
    const float* __restrict__ seg_emb,   const float* __restrict__ pe)
{
    const int token = blockIdx.x * 4 + (threadIdx.x >> 6);
    const int c     = (threadIdx.x & 63) * 4;
    const int b     = token >> 9;
    const int l     = token & (LL - 1);

    const int e  = __ldg(&element[token]);
    const int a  = __ldg(&aroma[token]);
    const int ch = __ldg(&charge[token]) + 6;
    const int s  = __ldg(&segment[token]);
    const int r  = __ldg(&rmask[token]);

    float4 v = *(const float4*)(elem_emb + e * DD + c);
    float4 t;
    t = *(const float4*)(pe + l * DD + c);          v.x += t.x; v.y += t.y; v.z += t.z; v.w += t.w;
    t = *(const float4*)(aroma_emb + a * DD + c);   v.x += t.x; v.y += t.y; v.z += t.z; v.w += t.w;
    t = *(const float4*)(charge_emb + ch * DD + c); v.x += t.x; v.y += t.y; v.z += t.z; v.w += t.w;
    t = *(const float4*)(seg_emb + s * DD + c);     v.x += t.x; v.y += t.y; v.z += t.z; v.w += t.w;
    t = *(const float4*)(react_emb + r * DD + c);   v.x += t.x; v.y += t.y; v.z += t.z; v.w += t.w;

    *(float4*)(g_emb + (l * BB + b) * DD + c) = v;
    float4 q = make_float4(tf32r(v.x), tf32r(v.y), tf32r(v.z), tf32r(v.w));
    *(float4*)(g_x + token * DD + c) = q;
}

// ---------------------------------------------------------------------------
// TF32 tensor-core GEMM via mma.sync:  C = A @ W^T + bias (+res) (+relu)
// Inputs pre-rounded to tf32 -> NO cvt in mainloop (12 LDSM + 32 MMA / chunk).
// BM=128, BN=128, BK=16, 4-stage cp.async pipeline, 8 warps, warp tile 64x32.
// WOUT: round the stored output to tf32 (when it feeds another GEMM).
// ---------------------------------------------------------------------------
#define BM     128
#define BN     128
#define BK     16
#define STAGES 4
#define STG_SZ 16384
#define SMEM_SZ (STAGES * STG_SZ)   // 65536

template<bool RELU, bool RES, bool WOUT>
__global__ __launch_bounds__(256, 2) void tgemm_kernel(
    const float* __restrict__ A, const float* __restrict__ W,
    const float* __restrict__ bias, const float* __restrict__ res,
    float* __restrict__ C, int N, int K)
{
    extern __shared__ char smem[];
    const uint32_t sbase = smem_u32(smem);
    const int tid = threadIdx.x;
    const int wid = tid >> 5;
    const int lid = tid & 31;
    const int wm  = wid & 1;        // warp row: 2 x 64
    const int wn  = wid >> 1;       // warp col: 4 x 32

    const int rowBase = blockIdx.y * BM;
    const int colBase = blockIdx.x * BN;

    const int NC = K / BK;

    auto load_stage = [&](int c) {
        const int k0 = c * BK;
        const uint32_t sA = sbase + (c % STAGES) * STG_SZ;
        const uint32_t sB = sA + 8192;
        const float* Ag = A + (size_t)rowBase * K + k0;
        const float* Wg = W + (size_t)colBase * K + k0;
        #pragma unroll
        for (int p = 0; p < 2; p++) {
            int v = tid + p * 256;
            int r = v >> 2, ck = v & 3;
            cpasync16(sA + r * 64 + ((ck ^ ((r >> 1) & 3)) * 16),
                      Ag + (size_t)r * K + ck * 4);
        }
        #pragma unroll
        for (int p = 0; p < 2; p++) {
            int v = tid + p * 256;
            int r = v >> 2, ck = v & 3;
            cpasync16(sB + r * 64 + ((ck ^ ((r >> 1) & 3)) * 16),
                      Wg + (size_t)r * K + ck * 4);
        }
        CP_COMMIT();
    };

    float acc[4][4][4];
    #pragma unroll
    for (int mi = 0; mi < 4; mi++)
        #pragma unroll
        for (int ni = 0; ni < 4; ni++)
            #pragma unroll
            for (int j = 0; j < 4; j++) acc[mi][ni][j] = 0.f;

    // per-thread ldmatrix address components
    const int t   = lid & 7;
    const int sel = lid >> 3;
    int aRow[4], aXor[4];
    #pragma unroll
    for (int mi = 0; mi < 4; mi++) {
        int r = wm * 64 + mi * 16 + (sel & 1) * 8 + t;
        aRow[mi] = r * 64;
        aXor[mi] = (r >> 1) & 3;
    }
    const int aCk = sel >> 1;
    int bRow[2], bXor[2];
    #pragma unroll
    for (int np = 0; np < 2; np++) {
        int r = wn * 32 + np * 16 + (sel >> 1) * 8 + t;
        bRow[np] = r * 64;
        bXor[np] = (r >> 1) & 3;
    }
    const int bCk = sel & 1;

    #pragma unroll
    for (int s = 0; s < STAGES - 1; s++) load_stage(s);

    for (int c = 0; c < NC; c++) {
        cpwait<STAGES - 2>();
        __syncthreads();
        if (c + STAGES - 1 < NC) load_stage(c + STAGES - 1);
        else CP_COMMIT();

        const uint32_t sA = sbase + (c % STAGES) * STG_SZ;
        const uint32_t sB = sA + 8192;

        #pragma unroll
        for (int ks = 0; ks < 2; ks++) {
            uint32_t af[4][4], bf[2][4];
            #pragma unroll
            for (int mi = 0; mi < 4; mi++) {
                int ck = ks * 2 + aCk;
                ldsm4(af[mi], sA + aRow[mi] + ((ck ^ aXor[mi]) * 16));
            }
            #pragma unroll
            for (int np = 0; np < 2; np++) {
                int ck = ks * 2 + bCk;
                ldsm4(bf[np], sB + bRow[np] + ((ck ^ bXor[np]) * 16));
            }
            #pragma unroll
            for (int mi = 0; mi < 4; mi++)
                #pragma unroll
                for (int ni = 0; ni < 4; ni++)
                    mma_tf32(acc[mi][ni], af[mi], &bf[ni >> 1][(ni & 1) * 2]);
        }
    }

    // ---- epilogue ----
    const int g  = lid >> 2;
    const int tg = lid & 3;
    #pragma unroll
    for (int mi = 0; mi < 4; mi++) {
        const int row0 = rowBase + wm * 64 + mi * 16 + g;
        const int row1 = row0 + 8;
        #pragma unroll
        for (int ni = 0; ni < 4; ni++) {
            const int col = colBase + wn * 32 + ni * 8 + tg * 2;
            float bx = __ldg(&bias[col]), by = __ldg(&bias[col + 1]);
            float2 v0 = make_float2(acc[mi][ni][0] + bx, acc[mi][ni][1] + by);
            float2 v1 = make_float2(acc[mi][ni][2] + bx, acc[mi][ni][3] + by);
            if (RES) {
                float2 r0 = *(const float2*)(res + (size_t)row0 * N + col);
                float2 r1 = *(const float2*)(res + (size_t)row1 * N + col);
                v0.x += r0.x; v0.y += r0.y; v1.x += r1.x; v1.y += r1.y;
            }
            if (RELU) {
                v0.x = fmaxf(v0.x, 0.f); v0.y = fmaxf(v0.y, 0.f);
                v1.x = fmaxf(v1.x, 0.f); v1.y = fmaxf(v1.y, 0.f);
            }
            if (WOUT) {
                v0.x = tf32r(v0.x); v0.y = tf32r(v0.y);
                v1.x = tf32r(v1.x); v1.y = tf32r(v1.y);
            }
            *(float2*)(C + (size_t)row0 * N + col) = v0;
            *(float2*)(C + (size_t)row1 * N + col) = v1;
        }
    }
}

// ---------------------------------------------------------------------------
// Bond aggregation + output
// ---------------------------------------------------------------------------
__global__ __launch_bounds__(256) void agg_kernel(
    const int* __restrict__ bond, float* __restrict__ out)
{
    const int token = blockIdx.x * 4 + (threadIdx.x >> 6);
    const int c     = (threadIdx.x & 63) * 4;
    const int b     = token >> 9;
    const int l     = token & (LL - 1);

    float4 acc = *(const float4*)(g_emb + (l * BB + b) * DD + c);
    const int* bd = bond + token * KKB;
    #pragma unroll
    for (int k = 0; k < KKB; k++) {
        const int j = __ldg(&bd[k]);
        if (j != l) {
            float4 m = *(const float4*)(g_msg + ((size_t)b * LL + j) * DD + c);
            acc.x += m.x; acc.y += m.y; acc.z += m.z; acc.w += m.w;
        }
    }
    *(float4*)(out + (l * BB + b) * DD + c) = acc;
}

// ---------------------------------------------------------------------------
// Launch (graph-capturable)
// ---------------------------------------------------------------------------
extern "C" void kernel_launch(void* const* d_in, const int* in_sizes, int n_in,
                              void* d_out, int out_size)
{
    const int*   element    = (const int*)  d_in[0];
    const int*   bond       = (const int*)  d_in[1];
    const int*   aroma      = (const int*)  d_in[2];
    const int*   charge     = (const int*)  d_in[3];
    const int*   segment    = (const int*)  d_in[4];
    const int*   rmask      = (const int*)  d_in[5];
    const float* elem_emb   = (const float*)d_in[6];
    const float* charge_emb = (const float*)d_in[7];
    const float* aroma_emb  = (const float*)d_in[8];
    const float* react_emb  = (const float*)d_in[9];
    const float* seg_emb    = (const float*)d_in[10];
    const float* pe         = (const float*)d_in[11];
    const float* w1 = (const float*)d_in[12];
    const float* b1 = (const float*)d_in[13];
    const float* w2 = (const float*)d_in[14];
    const float* b2 = (const float*)d_in[15];
    const float* w3 = (const float*)d_in[16];
    const float* b3 = (const float*)d_in[17];
    const float* w4 = (const float*)d_in[18];
    const float* b4 = (const float*)d_in[19];
    const float* w5 = (const float*)d_in[20];
    const float* b5 = (const float*)d_in[21];

    float *x, *h, *x2, *x3, *msg, *wr;
    cudaGetSymbolAddress((void**)&x,   g_x);
    cudaGetSymbolAddress((void**)&h,   g_h);
    cudaGetSymbolAddress((void**)&x2,  g_x2);
    cudaGetSymbolAddress((void**)&x3,  g_x3);
    cudaGetSymbolAddress((void**)&msg, g_msg);
    cudaGetSymbolAddress((void**)&wr,  g_wr);

    cudaFuncSetAttribute(tgemm_kernel<true,  false, true >,
                         cudaFuncAttributeMaxDynamicSharedMemorySize, SMEM_SZ);
    cudaFuncSetAttribute(tgemm_kernel<false, true,  true >,
                         cudaFuncAttributeMaxDynamicSharedMemorySize, SMEM_SZ);
    cudaFuncSetAttribute(tgemm_kernel<false, false, false>,
                         cudaFuncAttributeMaxDynamicSharedMemorySize, SMEM_SZ);

    // 0) pre-round weights to tf32
    round_w_kernel<<<(WTOTAL / 4 + 255) / 256, 256>>>(w1, w2, w3, w4, w5);

    // 1) embedding sum
    embed_kernel<<<MTOK / 4, 256>>>(element, aroma, charge, segment, rmask,
                                    elem_emb, charge_emb, aroma_emb,
                                    react_emb, seg_emb, pe);

    // 2) MLP block 1: h = relu(x @ w1^T + b1); x2 = x + h @ w2^T + b2
    tgemm_kernel<true,  false, true ><<<dim3(HID / BN, MTOK / BM), 256, SMEM_SZ>>>(
        x, wr + WOFF_W1, b1, nullptr, h, HID, DD);
    tgemm_kernel<false, true,  true ><<<dim3(DD / BN,  MTOK / BM), 256, SMEM_SZ>>>(
        h, wr + WOFF_W2, b2, x, x2, DD, HID);

    // 3) MLP block 2
    tgemm_kernel<true,  false, true ><<<dim3(HID / BN, MTOK / BM), 256, SMEM_SZ>>>(
        x2, wr + WOFF_W3, b3, nullptr, h, HID, DD);
    tgemm_kernel<false, true,  true ><<<dim3(DD / BN,  MTOK / BM), 256, SMEM_SZ>>>(
        h, wr + WOFF_W4, b4, x2, x3, DD, HID);

    // 4) msg = x3 @ w5^T + b5  (exact fp32 store)
    tgemm_kernel<false, false, false><<<dim3(DD / BN,  MTOK / BM), 256, SMEM_SZ>>>(
        x3, wr + WOFF_W5, b5, nullptr, msg, DD, DD);

    // 5) out = emb + masked bond aggregation
    agg_kernel<<<MTOK / 4, 256>>>(bond, (float*)d_out);
}

// round 10
// speedup vs baseline: 3.8975x; 1.0897x over previous
#include <cuda_runtime.h>
#include <cuda_bf16.h>
#include <cstdint>

// Problem constants
#define BB   32
#define LL   512
#define DD   256
#define KKB  6
#define MTOK (BB * LL)   // 16384 tokens
#define HID  (4 * DD)    // 1024

// ---------------------------------------------------------------------------
// Scratch (static __device__ arrays: allocation-guard safe)
// ---------------------------------------------------------------------------
__device__ float g_emb[MTOK * DD];   // [L][B][D] layout (exact fp32)
__device__ float g_x  [MTOK * DD];   // [token][D], tf32-rounded
__device__ float g_h  [MTOK * HID];  // hidden activations (tf32-rounded)
__device__ float g_x2 [MTOK * DD];   // tf32-rounded
__device__ float g_x3 [MTOK * DD];   // tf32-rounded
__device__ float g_msg[MTOK * DD];   // exact fp32
// pre-rounded weights, concatenated: w1 | w2 | w3 | w4 | w5
#define WOFF_W1 0
#define WOFF_W2 262144
#define WOFF_W3 524288
#define WOFF_W4 786432
#define WOFF_W5 1048576
#define WTOTAL  1114112
__device__ float g_wr[WTOTAL];

// ---------------------------------------------------------------------------
// PTX helpers (sm_80-compatible only: cp.async, ldmatrix, mma.sync)
// ---------------------------------------------------------------------------
__device__ __forceinline__ uint32_t smem_u32(const void* p) {
    uint32_t a;
    asm("{ .reg .u64 t; cvta.to.shared.u64 t, %1; cvt.u32.u64 %0, t; }"
        : "=r"(a) : "l"(p));
    return a;
}

__device__ __forceinline__ void cpasync16(uint32_t s, const void* g) {
    asm volatile("cp.async.cg.shared.global [%0], [%1], 16;" :: "r"(s), "l"(g));
}
#define CP_COMMIT() asm volatile("cp.async.commit_group;" ::: "memory")
template<int N> __device__ __forceinline__ void cpwait() {
    asm volatile("cp.async.wait_group %0;" :: "n"(N) : "memory");
}

__device__ __forceinline__ void ldsm4(uint32_t* r, uint32_t addr) {
    asm volatile("ldmatrix.sync.aligned.m8n8.x4.shared.b16 {%0,%1,%2,%3}, [%4];"
        : "=r"(r[0]), "=r"(r[1]), "=r"(r[2]), "=r"(r[3]) : "r"(addr));
}

__device__ __forceinline__ float tf32r(float x) {
    uint32_t u = __float_as_uint(x);
    asm("cvt.rna.tf32.f32 %0, %0;" : "+r"(u));
    return __uint_as_float(u);
}

__device__ __forceinline__ void mma_tf32(float* d, const uint32_t* a, const uint32_t* b) {
    asm volatile(
        "mma.sync.aligned.m16n8k8.row.col.f32.tf32.tf32.f32 "
        "{%0,%1,%2,%3}, {%4,%5,%6,%7}, {%8,%9}, {%0,%1,%2,%3};"
        : "+f"(d[0]), "+f"(d[1]), "+f"(d[2]), "+f"(d[3])
        : "r"(a[0]), "r"(a[1]), "r"(a[2]), "r"(a[3]), "r"(b[0]), "r"(b[1]));
}

// ---------------------------------------------------------------------------
// Weight pre-rounding: round all 5 weight matrices to tf32 once.
// ---------------------------------------------------------------------------
__global__ __launch_bounds__(256) void round_w_kernel(
    const float* __restrict__ w1, const float* __restrict__ w2,
    const float* __restrict__ w3, const float* __restrict__ w4,
    const float* __restrict__ w5)
{
    const int i = blockIdx.x * 256 + threadIdx.x;      // float4 index
    const size_t idx = (size_t)i * 4;
    if (idx >= WTOTAL) return;
    const float* s; size_t base;
    if      (idx < WOFF_W2) { s = w1; base = WOFF_W1; }
    else if (idx < WOFF_W3) { s = w2; base = WOFF_W2; }
    else if (idx < WOFF_W4) { s = w3; base = WOFF_W3; }
    else if (idx < WOFF_W5) { s = w4; base = WOFF_W4; }
    else                    { s = w5; base = WOFF_W5; }
    float4 v = *(const float4*)(s + (idx - base));
    v.x = tf32r(v.x); v.y = tf32r(v.y); v.z = tf32r(v.z); v.w = tf32r(v.w);
    *(float4*)(g_wr + idx) = v;
}

// ---------------------------------------------------------------------------
// Embedding sum: g_emb exact; g_x tf32-rounded (GEMM input)
// ---------------------------------------------------------------------------
__global__ __launch_bounds__(256) void embed_kernel(
    const int* __restrict__ element, const int* __restrict__ aroma,
    const int* __restrict__ charge,  const int* __restrict__ segment,
    const int* __restrict__ rmask,
    const float* __restrict__ elem_emb, const float* __restrict__ charge_emb,
    const float* __restrict__ aroma_emb, const float* __restrict__ react_emb,
    const float* __restrict__ seg_emb,   const float* __restrict__ pe)
{
    const int token = blockIdx.x * 4 + (threadIdx.x >> 6);
    const int c     = (threadIdx.x & 63) * 4;
    const int b     = token >> 9;
    const int l     = token & (LL - 1);

    const int e  = __ldg(&element[token]);
    const int a  = __ldg(&aroma[token]);
    const int ch = __ldg(&charge[token]) + 6;
    const int s  = __ldg(&segment[token]);
    const int r  = __ldg(&rmask[token]);

    float4 v = *(const float4*)(elem_emb + e * DD + c);
    float4 t;
    t = *(const float4*)(pe + l * DD + c);          v.x += t.x; v.y += t.y; v.z += t.z; v.w += t.w;
    t = *(const float4*)(aroma_emb + a * DD + c);   v.x += t.x; v.y += t.y; v.z += t.z; v.w += t.w;
    t = *(const float4*)(charge_emb + ch * DD + c); v.x += t.x; v.y += t.y; v.z += t.z; v.w += t.w;
    t = *(const float4*)(seg_emb + s * DD + c);     v.x += t.x; v.y += t.y; v.z += t.z; v.w += t.w;
    t = *(const float4*)(react_emb + r * DD + c);   v.x += t.x; v.y += t.y; v.z += t.z; v.w += t.w;

    *(float4*)(g_emb + (l * BB + b) * DD + c) = v;
    float4 q = make_float4(tf32r(v.x), tf32r(v.y), tf32r(v.z), tf32r(v.w));
    *(float4*)(g_x + token * DD + c) = q;
}

// ---------------------------------------------------------------------------
// TF32 tensor-core GEMM via mma.sync:  C = A @ W^T + bias (+res) (+relu)
// Inputs pre-rounded to tf32 -> no cvt in mainloop.
// BM=128, BN=128, BK=32 (4 ks-iters/chunk), 3-stage cp.async pipeline,
// 8 warps, warp tile 64x32. Outer chunk loop ROLLED (compile-time safety);
// stage indices cycle via counters (no runtime modulo).
// WOUT: round the stored output to tf32 (when it feeds another GEMM).
// ---------------------------------------------------------------------------
#define BM     128
#define BN     128
#define BK     32
#define STAGES 3
#define STG_SZ 32768                  // (BM + BN) * BK * 4
#define SMEM_SZ (STAGES * STG_SZ)     // 98304

template<int K, bool RELU, bool RES, bool WOUT>
__global__ __launch_bounds__(256, 2) void tgemm_kernel(
    const float* __restrict__ A, const float* __restrict__ W,
    const float* __restrict__ bias, const float* __restrict__ res,
    float* __restrict__ C, int N)
{
    extern __shared__ char smem[];
    const uint32_t sbase = smem_u32(smem);
    const int tid = threadIdx.x;
    const int wid = tid >> 5;
    const int lid = tid & 31;
    const int wm  = wid & 1;        // warp row: 2 x 64
    const int wn  = wid >> 1;       // warp col: 4 x 32

    const int rowBase = blockIdx.y * BM;
    const int colBase = blockIdx.x * BN;

    constexpr int NC = K / BK;

    // stage loader: A tile 128x32 f32 (16KB) + B tile 128x32 f32 (16KB)
    // smem row = 128B (32 floats), xor swizzle on 16B chunks within the row:
    // phys_chunk = ck ^ (row & 7) -> ldmatrix conflict-free
    auto load_stage = [&](int c, int buf) {
        const int k0 = c * BK;
        const uint32_t sA = sbase + buf * STG_SZ;
        const uint32_t sB = sA + 16384;
        const float* Ag = A + (size_t)rowBase * K + k0;
        const float* Wg = W + (size_t)colBase * K + k0;
        #pragma unroll
        for (int p = 0; p < 4; p++) {              // 1024 chunks / 256 thr
            int v = tid + p * 256;
            int r = v >> 3, ck = v & 7;
            cpasync16(sA + r * 128 + ((ck ^ (r & 7)) * 16),
                      Ag + (size_t)r * K + ck * 4);
        }
        #pragma unroll
        for (int p = 0; p < 4; p++) {
            int v = tid + p * 256;
            int r = v >> 3, ck = v & 7;
            cpasync16(sB + r * 128 + ((ck ^ (r & 7)) * 16),
                      Wg + (size_t)r * K + ck * 4);
        }
        CP_COMMIT();
    };

    float acc[4][4][4];
    #pragma unroll
    for (int mi = 0; mi < 4; mi++)
        #pragma unroll
        for (int ni = 0; ni < 4; ni++)
            #pragma unroll
            for (int j = 0; j < 4; j++) acc[mi][ni][j] = 0.f;

    // per-thread ldmatrix address components (row stride 128B, 8 chunks/row)
    const int t   = lid & 7;
    const int sel = lid >> 3;
    int aRow[4], aXor[4];
    #pragma unroll
    for (int mi = 0; mi < 4; mi++) {
        int r = wm * 64 + mi * 16 + (sel & 1) * 8 + t;
        aRow[mi] = r * 128;
        aXor[mi] = r & 7;
    }
    const int aCk = sel >> 1;
    int bRow[2], bXor[2];
    #pragma unroll
    for (int np = 0; np < 2; np++) {
        int r = wn * 32 + np * 16 + (sel >> 1) * 8 + t;
        bRow[np] = r * 128;
        bXor[np] = r & 7;
    }
    const int bCk = sel & 1;

    // prologue: stages 0, 1
    load_stage(0, 0);
    if (NC > 1) load_stage(1, 1);
    else        CP_COMMIT();

    int cbuf = 0;   // stage holding chunk c
    for (int c = 0; c < NC; c++) {      // ROLLED: compile-time safe
        cpwait<STAGES - 2>();
        __syncthreads();
        if (c + STAGES - 1 < NC) {
            int nbuf = cbuf + (STAGES - 1);
            if (nbuf >= STAGES) nbuf -= STAGES;
            load_stage(c + STAGES - 1, nbuf);
        } else {
            CP_COMMIT();
        }

        const uint32_t sA = sbase + cbuf * STG_SZ;
        const uint32_t sB = sA + 16384;

        #pragma unroll
        for (int ks = 0; ks < 4; ks++) {           // 4 x K=8 per chunk
            uint32_t af[4][4], bf[2][4];
            #pragma unroll
            for (int mi = 0; mi < 4; mi++) {
                int ck = ks * 2 + aCk;
                ldsm4(af[mi], sA + aRow[mi] + ((ck ^ aXor[mi]) * 16));
            }
            #pragma unroll
            for (int np = 0; np < 2; np++) {
                int ck = ks * 2 + bCk;
                ldsm4(bf[np], sB + bRow[np] + ((ck ^ bXor[np]) * 16));
            }
            #pragma unroll
            for (int mi = 0; mi < 4; mi++)
                #pragma unroll
                for (int ni = 0; ni < 4; ni++)
                    mma_tf32(acc[mi][ni], af[mi], &bf[ni >> 1][(ni & 1) * 2]);
        }

        if (++cbuf == STAGES) cbuf = 0;
    }

    // ---- epilogue ----
    const int g  = lid >> 2;
    const int tg = lid & 3;
    #pragma unroll
    for (int mi = 0; mi < 4; mi++) {
        const int row0 = rowBase + wm * 64 + mi * 16 + g;
        const int row1 = row0 + 8;
        #pragma unroll
        for (int ni = 0; ni < 4; ni++) {
            const int col = colBase + wn * 32 + ni * 8 + tg * 2;
            float bx = __ldg(&bias[col]), by = __ldg(&bias[col + 1]);
            float2 v0 = make_float2(acc[mi][ni][0] + bx, acc[mi][ni][1] + by);
            float2 v1 = make_float2(acc[mi][ni][2] + bx, acc[mi][ni][3] + by);
            if (RES) {
                float2 r0 = *(const float2*)(res + (size_t)row0 * N + col);
                float2 r1 = *(const float2*)(res + (size_t)row1 * N + col);
                v0.x += r0.x; v0.y += r0.y; v1.x += r1.x; v1.y += r1.y;
            }
            if (RELU) {
                v0.x = fmaxf(v0.x, 0.f); v0.y = fmaxf(v0.y, 0.f);
                v1.x = fmaxf(v1.x, 0.f); v1.y = fmaxf(v1.y, 0.f);
            }
            if (WOUT) {
                v0.x = tf32r(v0.x); v0.y = tf32r(v0.y);
                v1.x = tf32r(v1.x); v1.y = tf32r(v1.y);
            }
            *(float2*)(C + (size_t)row0 * N + col) = v0;
            *(float2*)(C + (size_t)row1 * N + col) = v1;
        }
    }
}

// ---------------------------------------------------------------------------
// Bond aggregation + output
// ---------------------------------------------------------------------------
__global__ __launch_bounds__(256) void agg_kernel(
    const int* __restrict__ bond, float* __restrict__ out)
{
    const int token = blockIdx.x * 4 + (threadIdx.x >> 6);
    const int c     = (threadIdx.x & 63) * 4;
    const int b     = token >> 9;
    const int l     = token & (LL - 1);

    float4 acc = *(const float4*)(g_emb + (l * BB + b) * DD + c);
    const int* bd = bond + token * KKB;
    #pragma unroll
    for (int k = 0; k < KKB; k++) {
        const int j = __ldg(&bd[k]);
        if (j != l) {
            float4 m = *(const float4*)(g_msg + ((size_t)b * LL + j) * DD + c);
            acc.x += m.x; acc.y += m.y; acc.z += m.z; acc.w += m.w;
        }
    }
    *(float4*)(out + (l * BB + b) * DD + c) = acc;
}

// ---------------------------------------------------------------------------
// Launch (graph-capturable)
// ---------------------------------------------------------------------------
extern "C" void kernel_launch(void* const* d_in, const int* in_sizes, int n_in,
                              void* d_out, int out_size)
{
    const int*   element    = (const int*)  d_in[0];
    const int*   bond       = (const int*)  d_in[1];
    const int*   aroma      = (const int*)  d_in[2];
    const int*   charge     = (const int*)  d_in[3];
    const int*   segment    = (const int*)  d_in[4];
    const int*   rmask      = (const int*)  d_in[5];
    const float* elem_emb   = (const float*)d_in[6];
    const float* charge_emb = (const float*)d_in[7];
    const float* aroma_emb  = (const float*)d_in[8];
    const float* react_emb  = (const float*)d_in[9];
    const float* seg_emb    = (const float*)d_in[10];
    const float* pe         = (const float*)d_in[11];
    const float* w1 = (const float*)d_in[12];
    const float* b1 = (const float*)d_in[13];
    const float* w2 = (const float*)d_in[14];
    const float* b2 = (const float*)d_in[15];
    const float* w3 = (const float*)d_in[16];
    const float* b3 = (const float*)d_in[17];
    const float* w4 = (const float*)d_in[18];
    const float* b4 = (const float*)d_in[19];
    const float* w5 = (const float*)d_in[20];
    const float* b5 = (const float*)d_in[21];

    float *x, *h, *x2, *x3, *msg, *wr;
    cudaGetSymbolAddress((void**)&x,   g_x);
    cudaGetSymbolAddress((void**)&h,   g_h);
    cudaGetSymbolAddress((void**)&x2,  g_x2);
    cudaGetSymbolAddress((void**)&x3,  g_x3);
    cudaGetSymbolAddress((void**)&msg, g_msg);
    cudaGetSymbolAddress((void**)&wr,  g_wr);

    cudaFuncSetAttribute(tgemm_kernel<DD,  true,  false, true >,
                         cudaFuncAttributeMaxDynamicSharedMemorySize, SMEM_SZ);
    cudaFuncSetAttribute(tgemm_kernel<HID, false, true,  true >,
                         cudaFuncAttributeMaxDynamicSharedMemorySize, SMEM_SZ);
    cudaFuncSetAttribute(tgemm_kernel<DD,  false, false, false>,
                         cudaFuncAttributeMaxDynamicSharedMemorySize, SMEM_SZ);

    // 0) pre-round weights to tf32
    round_w_kernel<<<(WTOTAL / 4 + 255) / 256, 256>>>(w1, w2, w3, w4, w5);

    // 1) embedding sum
    embed_kernel<<<MTOK / 4, 256>>>(element, aroma, charge, segment, rmask,
                                    elem_emb, charge_emb, aroma_emb,
                                    react_emb, seg_emb, pe);

    // 2) MLP block 1: h = relu(x @ w1^T + b1); x2 = x + h @ w2^T + b2
    tgemm_kernel<DD,  true,  false, true ><<<dim3(HID / BN, MTOK / BM), 256, SMEM_SZ>>>(
        x, wr + WOFF_W1, b1, nullptr, h, HID);
    tgemm_kernel<HID, false, true,  true ><<<dim3(DD / BN,  MTOK / BM), 256, SMEM_SZ>>>(
        h, wr + WOFF_W2, b2, x, x2, DD);

    // 3) MLP block 2
    tgemm_kernel<DD,  true,  false, true ><<<dim3(HID / BN, MTOK / BM), 256, SMEM_SZ>>>(
        x2, wr + WOFF_W3, b3, nullptr, h, HID);
    tgemm_kernel<HID, false, true,  true ><<<dim3(DD / BN,  MTOK / BM), 256, SMEM_SZ>>>(
        h, wr + WOFF_W4, b4, x2, x3, DD);

    // 4) msg = x3 @ w5^T + b5  (exact fp32 store)
    tgemm_kernel<DD,  false, false, false><<<dim3(DD / BN,  MTOK / BM), 256, SMEM_SZ>>>(
        x3, wr + WOFF_W5, b5, nullptr, msg, DD);

    // 5) out = emb + masked bond aggregation
    agg_kernel<<<MTOK / 4, 256>>>(bond, (float*)d_out);
}